// round 4
// baseline (speedup 1.0000x reference)
#include <cuda_runtime.h>

#define IMG_H 512
#define IMG_W 512
#define OUT_H 502
#define OUT_W 502
#define NIMG 32
#define HALO 10
#define STRIP 32      // output rows per block
#define TILE_W 256    // output cols per block
#define NTHREADS 256

// Global accumulators (scratch via __device__ globals — no allocation).
__device__ double g_mse_sum;
__device__ double g_ssim_sum;

__global__ void init_kernel() {
    g_mse_sum = 0.0;
    g_ssim_sum = 0.0;
}

__global__ __launch_bounds__(NTHREADS, 2)
void fused_mse_ssim(const float* __restrict__ pred, const float* __restrict__ targ)
{
    // Normalized 11-tap gaussian (sigma=1.5). Local const array + full unroll
    // -> ptxas constant-propagates into FFMA-imm (src1-imm form, rt_SMSP=1).
    const float GW[11] = {
        0.00102838f, 0.00759876f, 0.03600077f, 0.10936070f, 0.21300554f,
        0.26601172f,
        0.21300554f, 0.10936070f, 0.03600077f, 0.00759876f, 0.00102838f
    };

    // Double-buffered row of 4-channel values: (p, t, (p+t)^2, (p-t)^2)
    __shared__ float4 ch[2][TILE_W + HALO + 6];
    __shared__ float red_m[8], red_s[8];

    const int tid = threadIdx.x;
    const int x0  = blockIdx.x * TILE_W;   // 0 or 256
    const int y0  = blockIdx.y * STRIP;    // 0..480
    const int img = blockIdx.z;

    const int n_out_rows = min(STRIP, OUT_H - y0);        // 32 or 22
    const int n_in_rows  = n_out_rows + HALO;             // 42 or 32
    const int n_out_cols = min(TILE_W, OUT_W - x0);       // 256 or 246
    const int n_halo     = min(TILE_W + HALO, IMG_W - x0) - TILE_W; // 10 or 0
    const bool do_col    = (tid < n_out_cols);

    const float* __restrict__ pbase = pred + (size_t)img * (IMG_H * IMG_W) + x0;
    const float* __restrict__ tbase = targ + (size_t)img * (IMG_H * IMG_W) + x0;

    // Vertical ring buffers (registers): 11 rows x 4 channels
    float hist0[11], hist1[11], hist2[11], hist3[11];
#pragma unroll
    for (int j = 0; j < 11; ++j) { hist0[j] = hist1[j] = hist2[j] = hist3[j] = 0.f; }

    float mse_acc  = 0.f;
    float ssim_acc = 0.f;

    const float C1 = 1e-4f;   // (0.01)^2
    const float C2 = 9e-4f;   // (0.03)^2

    for (int r = 0; r < n_in_rows; ++r) {
        const int y = y0 + r;
        const float* prow = pbase + (size_t)y * IMG_W;
        const float* trow = tbase + (size_t)y * IMG_W;
        float4* chrow = ch[r & 1];

        const float p = prow[tid];
        const float t = trow[tid];
        // MSE ownership: this block owns input rows [y0, y0+32); thread owns
        // column x0+tid. Every input pixel counted exactly once across grid.
        if (r < STRIP) { float dd = p - t; mse_acc = fmaf(dd, dd, mse_acc); }
        {
            float s = p + t, d = p - t;
            chrow[tid] = make_float4(p, t, s * s, d * d);
        }
        if (tid < n_halo) {
            float p2 = prow[TILE_W + tid];
            float t2 = trow[TILE_W + tid];
            float s2 = p2 + t2, d2 = p2 - t2;
            chrow[TILE_W + tid] = make_float4(p2, t2, s2 * s2, d2 * d2);
        }
        __syncthreads();   // double buffer -> one barrier per row is sufficient

        // Horizontal 11-tap blur at (row r, col tid): float4 taps from smem
        float h0 = 0.f, h1 = 0.f, h2 = 0.f, h3 = 0.f;
#pragma unroll
        for (int k = 0; k < 11; ++k) {
            float4 v = chrow[tid + k];
            h0 = fmaf(GW[k], v.x, h0);
            h1 = fmaf(GW[k], v.y, h1);
            h2 = fmaf(GW[k], v.z, h2);
            h3 = fmaf(GW[k], v.w, h3);
        }

        // Push into vertical ring
#pragma unroll
        for (int j = 0; j < 10; ++j) {
            hist0[j] = hist0[j + 1];
            hist1[j] = hist1[j + 1];
            hist2[j] = hist2[j + 1];
            hist3[j] = hist3[j + 1];
        }
        hist0[10] = h0; hist1[10] = h1; hist2[10] = h2; hist3[10] = h3;

        if (r >= HALO && do_col) {
            // Vertical 11-tap blur (pure registers)
            float m1 = 0.f, m2 = 0.f, bs = 0.f, bd = 0.f;
#pragma unroll
            for (int j = 0; j < 11; ++j) {
                m1 = fmaf(GW[j], hist0[j], m1);
                m2 = fmaf(GW[j], hist1[j], m2);
                bs = fmaf(GW[j], hist2[j], bs);
                bd = fmaf(GW[j], hist3[j], bd);
            }
            // SSIM from 4 channels:
            //   blur(p^2)+blur(t^2) = (bs+bd)/2 ; blur(pt) = (bs-bd)/4
            float m1s = m1 * m1, m2s = m2 * m2, m12 = m1 * m2;
            float sigsum = fmaf(0.5f,  bs + bd, -(m1s + m2s));  // sigma1^2+sigma2^2
            float sig12  = fmaf(0.25f, bs - bd, -m12);          // sigma12
            float num = (2.f * m12 + C1) * (2.f * sig12 + C2);
            float den = fmaf(m1s + m2s + C1, sigsum + C2, 1e-6f);
            ssim_acc += __fdividef(num, den);
        }
    }

    // Block reduction
#pragma unroll
    for (int off = 16; off > 0; off >>= 1) {
        mse_acc  += __shfl_down_sync(0xffffffffu, mse_acc,  off);
        ssim_acc += __shfl_down_sync(0xffffffffu, ssim_acc, off);
    }
    const int wrp = tid >> 5, lane = tid & 31;
    if (lane == 0) { red_m[wrp] = mse_acc; red_s[wrp] = ssim_acc; }
    __syncthreads();
    if (tid == 0) {
        float m = 0.f, s = 0.f;
#pragma unroll
        for (int w = 0; w < 8; ++w) { m += red_m[w]; s += red_s[w]; }
        atomicAdd(&g_mse_sum,  (double)m);
        atomicAdd(&g_ssim_sum, (double)s);
    }
}

__global__ void finalize_kernel(float* out)
{
    const double mse_n  = (double)NIMG * IMG_H * IMG_W;   // 8388608
    const double ssim_n = (double)NIMG * OUT_H * OUT_W;   // 8064128
    double mse_loss  = g_mse_sum / mse_n;
    double ssim_loss = 1.0 - g_ssim_sum / ssim_n;
    out[0] = (float)(0.6 * mse_loss + 0.4 * ssim_loss);
}

extern "C" void kernel_launch(void* const* d_in, const int* in_sizes, int n_in,
                              void* d_out, int out_size)
{
    const float* pred = (const float*)d_in[0];
    const float* targ = (const float*)d_in[1];

    init_kernel<<<1, 1>>>();
    dim3 grid(2, (OUT_H + STRIP - 1) / STRIP, NIMG);  // (2, 16, 32) = 1024 blocks
    fused_mse_ssim<<<grid, NTHREADS>>>(pred, targ);
    finalize_kernel<<<1, 1>>>((float*)d_out);
}

// round 5
// speedup vs baseline: 1.4102x; 1.4102x over previous
#include <cuda_runtime.h>

#define IMG_H 512
#define IMG_W 512
#define OUT_H 502
#define OUT_W 502
#define NIMG 32
#define HALO 10
#define STRIP 32          // output rows per block (last strip: 22)
#define NTHREADS 256
#define NBLOCKS (16 * NIMG)   // 512

// Per-block partial sums (no init kernel, no atomics): [block][0]=mse, [1]=ssim
__device__ float g_partial[NBLOCKS * 2];

__global__ __launch_bounds__(NTHREADS, 1)
void fused_mse_ssim(const float* __restrict__ pred, const float* __restrict__ targ)
{
    // 11-tap gaussian (sigma=1.5), normalized. Local const + full unroll -> FFMA-imm.
    const float GW[11] = {
        0.00102838f, 0.00759876f, 0.03600077f, 0.10936070f, 0.21300554f,
        0.26601172f,
        0.21300554f, 0.10936070f, 0.03600077f, 0.00759876f, 0.00102838f
    };
    const float C1 = 1e-4f, C2 = 9e-4f;

    // SoA channels, double-buffered by input-row parity. 528 = 512 + tap pad.
    __shared__ float sbuf[2][4][528];      // [parity][ch: s,d,ss,dd][col]
    __shared__ float red_m[8], red_s[8];

    const int tid = threadIdx.x;
    const int c0  = 2 * tid;               // this thread's two columns
    const int y0  = blockIdx.x * STRIP;
    const int img = blockIdx.y;

    const int n_out = min(STRIP, OUT_H - y0);   // 32 or 22
    const int n_in  = n_out + HALO;             // 42 or 32

    const float* __restrict__ pbase = pred + (size_t)img * (IMG_H * IMG_W);
    const float* __restrict__ tbase = targ + (size_t)img * (IMG_H * IMG_W);

    // Streaming vertical accumulators: 11 in-flight output rows x 8 values
    // layout: [slot][0]=S0 [1]=S1 [2]=D0 [3]=D1 [4]=SS0 [5]=SS1 [6]=DD0 [7]=DD1
    float acc[11][8];
#pragma unroll
    for (int sl = 0; sl < 11; ++sl)
#pragma unroll
        for (int c = 0; c < 8; ++c) acc[sl][c] = 0.f;

    float mse_acc = 0.f, ssim_acc = 0.f;
    const bool emit_col = (tid <= 250);   // cols c0, c0+1 both < 502

    // Preload row 0
    float2 pp = ((const float2*)(pbase + (size_t)y0 * IMG_W))[tid];
    float2 tt = ((const float2*)(tbase + (size_t)y0 * IMG_W))[tid];

    for (int rb = 0; rb < 44; rb += 11) {
#pragma unroll
        for (int j = 0; j < 11; ++j) {
            const int r = rb + j;          // j static, rb multiple of 11
            if (r < n_in) {                // uniform predicate (barrier-safe)
                // Channels for this row from preloaded values
                float s0 = pp.x + tt.x, d0 = pp.x - tt.x;
                float s1 = pp.y + tt.y, d1 = pp.y - tt.y;
                if (r < STRIP) {           // MSE: exact tile ownership
                    mse_acc = fmaf(d0, d0, mse_acc);
                    mse_acc = fmaf(d1, d1, mse_acc);
                }
                float (*buf)[528] = sbuf[r & 1];
                ((float2*)&buf[0][c0])[0] = make_float2(s0, s1);
                ((float2*)&buf[1][c0])[0] = make_float2(d0, d1);
                ((float2*)&buf[2][c0])[0] = make_float2(s0 * s0, s1 * s1);
                ((float2*)&buf[3][c0])[0] = make_float2(d0 * d0, d1 * d1);

                // Prefetch next row before the barrier (hide LDG latency)
                if (r + 1 < n_in) {
                    const size_t off = (size_t)(y0 + r + 1) * IMG_W;
                    pp = ((const float2*)(pbase + off))[tid];
                    tt = ((const float2*)(tbase + off))[tid];
                }
                __syncthreads();

                // Horizontal 11-tap blur for 2 adjacent output cols, 4 channels.
                float hv[8];
#pragma unroll
                for (int chn = 0; chn < 4; ++chn) {
                    float v[12];
#pragma unroll
                    for (int m = 0; m < 6; ++m) {
                        float2 w = ((const float2*)&buf[chn][c0 + 2 * m])[0];
                        v[2 * m] = w.x; v[2 * m + 1] = w.y;
                    }
                    float a0 = 0.f, a1 = 0.f;
#pragma unroll
                    for (int k = 0; k < 11; ++k) {
                        a0 = fmaf(GW[k], v[k], a0);
                        a1 = fmaf(GW[k], v[k + 1], a1);
                    }
                    // order: S0,S1,D0,D1,SS0,SS1,DD0,DD1
                    hv[2 * chn] = a0; hv[2 * chn + 1] = a1;
                }

                // Vertical streaming: assignment (d=0) resets slot j, then adds.
#pragma unroll
                for (int c = 0; c < 8; ++c) acc[j][c] = GW[0] * hv[c];
#pragma unroll
                for (int d = 1; d < 11; ++d) {
                    const int sl = (j - d + 11) % 11;   // static
#pragma unroll
                    for (int c = 0; c < 8; ++c)
                        acc[sl][c] = fmaf(GW[d], hv[c], acc[sl][c]);
                }

                // Emit completed output row o = r - 10 (slot (j+1)%11)
                if (r >= HALO && emit_col) {
                    const int es = (j + 1) % 11;        // static
#pragma unroll
                    for (int col = 0; col < 2; ++col) {
                        float S  = acc[es][0 + col];
                        float D  = acc[es][2 + col];
                        float BS = acc[es][4 + col];
                        float BD = acc[es][6 + col];
                        float A = S * S, B = D * D;
                        float num1 = 0.5f * (A - B) + C1;
                        float den1 = 0.5f * (A + B) + C1;
                        float num2 = 0.5f * ((BS - BD) - (A - B)) + C2;
                        float den2 = 0.5f * ((BS + BD) - (A + B)) + C2;
                        ssim_acc += __fdividef(num1 * num2,
                                               fmaf(den1, den2, 1e-6f));
                    }
                }
            }
        }
    }

    // Block reduction -> per-block partials (no atomics)
#pragma unroll
    for (int off = 16; off > 0; off >>= 1) {
        mse_acc  += __shfl_down_sync(0xffffffffu, mse_acc,  off);
        ssim_acc += __shfl_down_sync(0xffffffffu, ssim_acc, off);
    }
    const int wrp = tid >> 5, lane = tid & 31;
    if (lane == 0) { red_m[wrp] = mse_acc; red_s[wrp] = ssim_acc; }
    __syncthreads();
    if (tid == 0) {
        float m = 0.f, s = 0.f;
#pragma unroll
        for (int w = 0; w < 8; ++w) { m += red_m[w]; s += red_s[w]; }
        const int bid = blockIdx.y * 16 + blockIdx.x;
        g_partial[bid * 2 + 0] = m;
        g_partial[bid * 2 + 1] = s;
    }
}

__global__ __launch_bounds__(256, 1)
void finalize_kernel(float* out)
{
    __shared__ double sm[8], ss[8];
    const int tid = threadIdx.x;
    double m = 0.0, s = 0.0;
    for (int i = tid; i < NBLOCKS; i += 256) {
        m += (double)g_partial[i * 2 + 0];
        s += (double)g_partial[i * 2 + 1];
    }
#pragma unroll
    for (int off = 16; off > 0; off >>= 1) {
        m += __shfl_down_sync(0xffffffffu, m, off);
        s += __shfl_down_sync(0xffffffffu, s, off);
    }
    if ((tid & 31) == 0) { sm[tid >> 5] = m; ss[tid >> 5] = s; }
    __syncthreads();
    if (tid == 0) {
        double M = 0.0, S = 0.0;
#pragma unroll
        for (int w = 0; w < 8; ++w) { M += sm[w]; S += ss[w]; }
        const double mse_n  = (double)NIMG * IMG_H * IMG_W;
        const double ssim_n = (double)NIMG * OUT_H * OUT_W;
        double mse_loss  = M / mse_n;
        double ssim_loss = 1.0 - S / ssim_n;
        out[0] = (float)(0.6 * mse_loss + 0.4 * ssim_loss);
    }
}

extern "C" void kernel_launch(void* const* d_in, const int* in_sizes, int n_in,
                              void* d_out, int out_size)
{
    const float* pred = (const float*)d_in[0];
    const float* targ = (const float*)d_in[1];

    dim3 grid(16, NIMG, 1);   // 16 row-strips x 32 images = 512 blocks
    fused_mse_ssim<<<grid, NTHREADS>>>(pred, targ);
    finalize_kernel<<<1, 256>>>((float*)d_out);
}

// round 6
// speedup vs baseline: 1.7074x; 1.2108x over previous
#include <cuda_runtime.h>

#define IMG_H 512
#define IMG_W 512
#define OUT_H 502
#define OUT_W 502
#define NIMG 32
#define HALO 10
#define STRIP 32          // output rows per block (last strip: 22)
#define NTHREADS 256
#define NBLOCKS (16 * NIMG)   // 512

__device__ float g_partial[NBLOCKS * 2];
__device__ unsigned g_count = 0;

// ---- packed f32x2 helpers (ptxas never fuses these from C++) ----
typedef unsigned long long u64t;
__device__ __forceinline__ u64t pk2(float lo, float hi) {
    u64t r; asm("mov.b64 %0, {%1,%2};" : "=l"(r) : "f"(lo), "f"(hi)); return r;
}
__device__ __forceinline__ void upk2(u64t v, float& lo, float& hi) {
    asm("mov.b64 {%0,%1}, %2;" : "=f"(lo), "=f"(hi) : "l"(v));
}
__device__ __forceinline__ u64t fma2(u64t a, u64t b, u64t c) {
    u64t d; asm("fma.rn.f32x2 %0, %1, %2, %3;" : "=l"(d) : "l"(a), "l"(b), "l"(c)); return d;
}
__device__ __forceinline__ u64t mul2(u64t a, u64t b) {
    u64t d; asm("mul.rn.f32x2 %0, %1, %2;" : "=l"(d) : "l"(a), "l"(b)); return d;
}

// Horizontal 11-tap blur for 2 adjacent output cols (c0, c0+1), one channel.
// Returns packed (out_c0, out_c0+1).
__device__ __forceinline__ u64t hblur(const float* __restrict__ ch, int c0,
                                      const u64t* __restrict__ GWP)
{
    const float2* b = (const float2*)(ch + c0);   // c0 even -> 8B aligned
    float2 w[6];
#pragma unroll
    for (int m = 0; m < 6; ++m) w[m] = b[m];
    u64t h = mul2(GWP[0], pk2(w[0].x, w[0].y));
#pragma unroll
    for (int k = 1; k < 11; ++k) {
        u64t P = (k & 1) ? pk2(w[k >> 1].y, w[(k >> 1) + 1].x)
                         : pk2(w[k >> 1].x, w[k >> 1].y);
        h = fma2(GWP[k], P, h);
    }
    return h;
}

__global__ __launch_bounds__(NTHREADS)
void fused_mse_ssim(const float* __restrict__ pred, const float* __restrict__ targ,
                    float* __restrict__ out)
{
    const float GW[11] = {
        0.00102838f, 0.00759876f, 0.03600077f, 0.10936070f, 0.21300554f,
        0.26601172f,
        0.21300554f, 0.10936070f, 0.03600077f, 0.00759876f, 0.00102838f
    };
    u64t GWP[11];
#pragma unroll
    for (int k = 0; k < 11; ++k) GWP[k] = pk2(GW[k], GW[k]);
    const float C1 = 1e-4f, C2 = 9e-4f;

    // SoA channels (p, t, s^2, d^2), double-buffered. 528 = 512 + tap pad.
    __shared__ float sbuf[2][4][528];
    __shared__ float red_m[8], red_s[8];
    __shared__ unsigned s_ticket;

    const int tid = threadIdx.x;
    const int c0  = 2 * tid;
    const int y0  = blockIdx.x * STRIP;
    const int img = blockIdx.y;

    const int n_out = min(STRIP, OUT_H - y0);
    const int n_in  = n_out + HALO;             // 42 or 32

    const float* __restrict__ pbase = pred + (size_t)img * (IMG_H * IMG_W);
    const float* __restrict__ tbase = targ + (size_t)img * (IMG_H * IMG_W);

    // Vertical streaming accumulators: 11 slots x 4 channels, column-pair packed
    u64t acc[11][4];
#pragma unroll
    for (int sl = 0; sl < 11; ++sl)
#pragma unroll
        for (int c = 0; c < 4; ++c) acc[sl][c] = 0ull;

    float mse_acc = 0.f, ssim_acc = 0.f;
    const bool emit_col = (tid <= 250);

    float2 pp = ((const float2*)(pbase + (size_t)y0 * IMG_W))[tid];
    float2 tt = ((const float2*)(tbase + (size_t)y0 * IMG_W))[tid];

    for (int rb = 0; rb < 44; rb += 11) {
#pragma unroll
        for (int j = 0; j < 11; ++j) {
            const int r = rb + j;
            if (r < n_in) {                 // block-uniform (barrier-safe)
                float d0 = pp.x - tt.x, s0 = pp.x + tt.x;
                float d1 = pp.y - tt.y, s1 = pp.y + tt.y;
                if (r < STRIP) {            // MSE: exact tile ownership
                    mse_acc = fmaf(d0, d0, mse_acc);
                    mse_acc = fmaf(d1, d1, mse_acc);
                }
                float (*buf)[528] = sbuf[r & 1];
                ((float2*)&buf[0][c0])[0] = pp;
                ((float2*)&buf[1][c0])[0] = tt;
                ((float2*)&buf[2][c0])[0] = make_float2(s0 * s0, s1 * s1);
                ((float2*)&buf[3][c0])[0] = make_float2(d0 * d0, d1 * d1);

                if (r + 1 < n_in) {         // prefetch next row (hide LDG)
                    const size_t off = (size_t)(y0 + r + 1) * IMG_W;
                    pp = ((const float2*)(pbase + off))[tid];
                    tt = ((const float2*)(tbase + off))[tid];
                }
                __syncthreads();

                // Horizontal blur: 4 channels, packed column pairs
                u64t hv[4];
#pragma unroll
                for (int chn = 0; chn < 4; ++chn)
                    hv[chn] = hblur(buf[chn], c0, GWP);

                // Vertical streaming (packed): reset slot j, add into others
#pragma unroll
                for (int c = 0; c < 4; ++c) acc[j][c] = mul2(GWP[0], hv[c]);
#pragma unroll
                for (int d = 1; d < 11; ++d) {
                    const int sl = (j - d + 11) % 11;   // static
#pragma unroll
                    for (int c = 0; c < 4; ++c)
                        acc[sl][c] = fma2(GWP[d], hv[c], acc[sl][c]);
                }

                // Emit completed output row o = r - 10 (slot (j+1)%11)
                if (r >= HALO && emit_col) {
                    const int es = (j + 1) % 11;        // static
                    float M1[2], M2[2], BS[2], BD[2];
                    upk2(acc[es][0], M1[0], M1[1]);
                    upk2(acc[es][1], M2[0], M2[1]);
                    upk2(acc[es][2], BS[0], BS[1]);
                    upk2(acc[es][3], BD[0], BD[1]);
#pragma unroll
                    for (int col = 0; col < 2; ++col) {
                        float m1s = M1[col] * M1[col];
                        float m2s = M2[col] * M2[col];
                        float m12 = M1[col] * M2[col];
                        float sums = m1s + m2s;
                        float sigsum = fmaf(0.5f,  BS[col] + BD[col], -sums);
                        float sig12  = fmaf(0.25f, BS[col] - BD[col], -m12);
                        float num = (2.f * m12 + C1) * (2.f * sig12 + C2);
                        float den = fmaf(sums + C1, sigsum + C2, 1e-6f);
                        ssim_acc += __fdividef(num, den);
                    }
                }
            }
        }
    }

    // Block reduction
#pragma unroll
    for (int off = 16; off > 0; off >>= 1) {
        mse_acc  += __shfl_down_sync(0xffffffffu, mse_acc,  off);
        ssim_acc += __shfl_down_sync(0xffffffffu, ssim_acc, off);
    }
    const int wrp = tid >> 5, lane = tid & 31;
    if (lane == 0) { red_m[wrp] = mse_acc; red_s[wrp] = ssim_acc; }
    __syncthreads();
    if (tid == 0) {
        float m = 0.f, s = 0.f;
#pragma unroll
        for (int w = 0; w < 8; ++w) { m += red_m[w]; s += red_s[w]; }
        const int bid = blockIdx.y * 16 + blockIdx.x;
        g_partial[bid * 2 + 0] = m;
        g_partial[bid * 2 + 1] = s;
        __threadfence();
        s_ticket = atomicAdd(&g_count, 1u);
    }
    __syncthreads();

    // Last block to finish folds in the final reduction (no 2nd launch)
    if (s_ticket == NBLOCKS - 1) {
        __threadfence();
        double m = 0.0, s = 0.0;
        for (int i = tid; i < NBLOCKS; i += NTHREADS) {
            m += (double)g_partial[i * 2 + 0];
            s += (double)g_partial[i * 2 + 1];
        }
#pragma unroll
        for (int off = 16; off > 0; off >>= 1) {
            m += __shfl_down_sync(0xffffffffu, m, off);
            s += __shfl_down_sync(0xffffffffu, s, off);
        }
        __shared__ double sm[8], ss[8];
        if (lane == 0) { sm[wrp] = m; ss[wrp] = s; }
        __syncthreads();
        if (tid == 0) {
            double M = 0.0, S = 0.0;
#pragma unroll
            for (int w = 0; w < 8; ++w) { M += sm[w]; S += ss[w]; }
            const double mse_n  = (double)NIMG * IMG_H * IMG_W;
            const double ssim_n = (double)NIMG * OUT_H * OUT_W;
            double mse_loss  = M / mse_n;
            double ssim_loss = 1.0 - S / ssim_n;
            out[0] = (float)(0.6 * mse_loss + 0.4 * ssim_loss);
            g_count = 0;   // self-reset for next graph replay
        }
    }
}

extern "C" void kernel_launch(void* const* d_in, const int* in_sizes, int n_in,
                              void* d_out, int out_size)
{
    const float* pred = (const float*)d_in[0];
    const float* targ = (const float*)d_in[1];

    dim3 grid(16, NIMG, 1);   // 16 row-strips x 32 images = 512 blocks
    fused_mse_ssim<<<grid, NTHREADS>>>(pred, targ, (float*)d_out);
}

// round 7
// speedup vs baseline: 1.8231x; 1.0678x over previous
#include <cuda_runtime.h>

#define IMG_H 512
#define IMG_W 512
#define OUT_H 502
#define OUT_W 502
#define NIMG 32
#define HALO 10
#define STRIP 28          // output rows per block (18 strips: 17x28 + 26)
#define NSTRIPS 18
#define NTHREADS 256
#define NBLOCKS (NSTRIPS * NIMG)   // 576 = 97.3% of 2 full waves at occ 2

__device__ float g_partial[NBLOCKS * 2];
__device__ unsigned g_count = 0;

// ---- packed f32x2 helpers (ptxas never fuses these from C++) ----
typedef unsigned long long u64t;
__device__ __forceinline__ u64t pk2(float lo, float hi) {
    u64t r; asm("mov.b64 %0, {%1,%2};" : "=l"(r) : "f"(lo), "f"(hi)); return r;
}
__device__ __forceinline__ void upk2(u64t v, float& lo, float& hi) {
    asm("mov.b64 {%0,%1}, %2;" : "=f"(lo), "=f"(hi) : "l"(v));
}
__device__ __forceinline__ u64t fma2(u64t a, u64t b, u64t c) {
    u64t d; asm("fma.rn.f32x2 %0, %1, %2, %3;" : "=l"(d) : "l"(a), "l"(b), "l"(c)); return d;
}
__device__ __forceinline__ u64t mul2(u64t a, u64t b) {
    u64t d; asm("mul.rn.f32x2 %0, %1, %2;" : "=l"(d) : "l"(a), "l"(b)); return d;
}

// Horizontal 11-tap blur for 2 adjacent output cols (c0, c0+1), one channel.
__device__ __forceinline__ u64t hblur(const float* __restrict__ ch, int c0,
                                      const u64t* __restrict__ GWP)
{
    const float2* b = (const float2*)(ch + c0);   // c0 even -> 8B aligned
    float2 w[6];
#pragma unroll
    for (int m = 0; m < 6; ++m) w[m] = b[m];
    u64t h = mul2(GWP[0], pk2(w[0].x, w[0].y));
#pragma unroll
    for (int k = 1; k < 11; ++k) {
        u64t P = (k & 1) ? pk2(w[k >> 1].y, w[(k >> 1) + 1].x)
                         : pk2(w[k >> 1].x, w[k >> 1].y);
        h = fma2(GWP[k], P, h);
    }
    return h;
}

__global__ __launch_bounds__(NTHREADS, 2)
void fused_mse_ssim(const float* __restrict__ pred, const float* __restrict__ targ,
                    float* __restrict__ out)
{
    const float GW[11] = {
        0.00102838f, 0.00759876f, 0.03600077f, 0.10936070f, 0.21300554f,
        0.26601172f,
        0.21300554f, 0.10936070f, 0.03600077f, 0.00759876f, 0.00102838f
    };
    u64t GWP[11];
#pragma unroll
    for (int k = 0; k < 11; ++k) GWP[k] = pk2(GW[k], GW[k]);
    const float C1 = 1e-4f, C2 = 9e-4f;

    // SoA channels (p, t, s^2, d^2); double-buffered by PAIR parity; 2 rows/pair.
    __shared__ float sbuf[2][4][2][528];   // [pair parity][ch][row-in-pair][col]
    __shared__ float red_m[8], red_s[8];
    __shared__ unsigned s_ticket;

    const int tid = threadIdx.x;
    const int c0  = 2 * tid;
    const int y0  = blockIdx.x * STRIP;
    const int img = blockIdx.y;

    const int n_out    = min(STRIP, OUT_H - y0);    // 28 or 26
    const int n_in     = n_out + HALO;              // 38 or 36 (always even)
    const int mse_rows = min(IMG_H - y0, (blockIdx.x == NSTRIPS - 1) ? 999 : STRIP);

    const float* __restrict__ pbase = pred + (size_t)img * (IMG_H * IMG_W);
    const float* __restrict__ tbase = targ + (size_t)img * (IMG_H * IMG_W);

    // Vertical streaming accumulators: 11 slots x 4 channels, column-pair packed
    u64t acc[11][4];
#pragma unroll
    for (int sl = 0; sl < 11; ++sl)
#pragma unroll
        for (int c = 0; c < 4; ++c) acc[sl][c] = 0ull;

    float mse_acc = 0.f, ssim_acc = 0.f;
    const bool emit_col = (tid <= 250);

    // Preload rows 0 and 1
    float2 pp0 = ((const float2*)(pbase + (size_t)(y0 + 0) * IMG_W))[tid];
    float2 tt0 = ((const float2*)(tbase + (size_t)(y0 + 0) * IMG_W))[tid];
    float2 pp1 = ((const float2*)(pbase + (size_t)(y0 + 1) * IMG_W))[tid];
    float2 tt1 = ((const float2*)(tbase + (size_t)(y0 + 1) * IMG_W))[tid];

    for (int rb = 0; rb < 44; rb += 22) {          // 22 rows ≡ 0 (mod 11)
#pragma unroll
        for (int pj = 0; pj < 11; ++pj) {
            const int r0 = rb + 2 * pj;            // even row of pair
            const int r1 = r0 + 1;
            const int j0 = (2 * pj) % 11;          // static slot indices
            const int j1 = (2 * pj + 1) % 11;
            if (r0 < n_in) {                       // block-uniform
                const bool has1 = (r1 < n_in);     // block-uniform
                const int par = pj & 1;            // pair parity (rb=22 flips 11 pairs -> same (r0/2)&1? no: use (r0>>1)&1)
                const int par2 = (r0 >> 1) & 1;
                (void)par;

                // ---- channel prep + MSE + STS for both rows ----
                {
                    float d0 = pp0.x - tt0.x, s0 = pp0.x + tt0.x;
                    float d1 = pp0.y - tt0.y, s1 = pp0.y + tt0.y;
                    if (r0 < mse_rows) {
                        mse_acc = fmaf(d0, d0, mse_acc);
                        mse_acc = fmaf(d1, d1, mse_acc);
                    }
                    ((float2*)&sbuf[par2][0][0][c0])[0] = pp0;
                    ((float2*)&sbuf[par2][1][0][c0])[0] = tt0;
                    ((float2*)&sbuf[par2][2][0][c0])[0] = make_float2(s0 * s0, s1 * s1);
                    ((float2*)&sbuf[par2][3][0][c0])[0] = make_float2(d0 * d0, d1 * d1);
                }
                if (has1) {
                    float d0 = pp1.x - tt1.x, s0 = pp1.x + tt1.x;
                    float d1 = pp1.y - tt1.y, s1 = pp1.y + tt1.y;
                    if (r1 < mse_rows) {
                        mse_acc = fmaf(d0, d0, mse_acc);
                        mse_acc = fmaf(d1, d1, mse_acc);
                    }
                    ((float2*)&sbuf[par2][0][1][c0])[0] = pp1;
                    ((float2*)&sbuf[par2][1][1][c0])[0] = tt1;
                    ((float2*)&sbuf[par2][2][1][c0])[0] = make_float2(s0 * s0, s1 * s1);
                    ((float2*)&sbuf[par2][3][1][c0])[0] = make_float2(d0 * d0, d1 * d1);
                }

                // ---- prefetch next pair (hide LDG latency across barrier) ----
                if (r0 + 2 < n_in) {
                    const size_t off = (size_t)(y0 + r0 + 2) * IMG_W;
                    pp0 = ((const float2*)(pbase + off))[tid];
                    tt0 = ((const float2*)(tbase + off))[tid];
                }
                if (r1 + 2 < n_in) {
                    const size_t off = (size_t)(y0 + r1 + 2) * IMG_W;
                    pp1 = ((const float2*)(pbase + off))[tid];
                    tt1 = ((const float2*)(tbase + off))[tid];
                }
                __syncthreads();

                // ---- row0: horizontal blur + vertical streaming + emit ----
                {
                    u64t hv[4];
#pragma unroll
                    for (int chn = 0; chn < 4; ++chn)
                        hv[chn] = hblur(&sbuf[par2][chn][0][0], c0, GWP);
#pragma unroll
                    for (int c = 0; c < 4; ++c) acc[j0][c] = mul2(GWP[0], hv[c]);
#pragma unroll
                    for (int d = 1; d < 11; ++d) {
                        const int sl = (j0 - d + 11) % 11;
#pragma unroll
                        for (int c = 0; c < 4; ++c)
                            acc[sl][c] = fma2(GWP[d], hv[c], acc[sl][c]);
                    }
                    if (r0 >= HALO && emit_col) {
                        const int es = (j0 + 1) % 11;
                        float M1[2], M2[2], BS[2], BD[2];
                        upk2(acc[es][0], M1[0], M1[1]);
                        upk2(acc[es][1], M2[0], M2[1]);
                        upk2(acc[es][2], BS[0], BS[1]);
                        upk2(acc[es][3], BD[0], BD[1]);
#pragma unroll
                        for (int col = 0; col < 2; ++col) {
                            float m1s = M1[col] * M1[col];
                            float m2s = M2[col] * M2[col];
                            float m12 = M1[col] * M2[col];
                            float sums = m1s + m2s;
                            float sigsum = fmaf(0.5f,  BS[col] + BD[col], -sums);
                            float sig12  = fmaf(0.25f, BS[col] - BD[col], -m12);
                            float num = (2.f * m12 + C1) * (2.f * sig12 + C2);
                            float den = fmaf(sums + C1, sigsum + C2, 1e-6f);
                            ssim_acc += __fdividef(num, den);
                        }
                    }
                }

                // ---- row1 ----
                if (has1) {
                    u64t hv[4];
#pragma unroll
                    for (int chn = 0; chn < 4; ++chn)
                        hv[chn] = hblur(&sbuf[par2][chn][1][0], c0, GWP);
#pragma unroll
                    for (int c = 0; c < 4; ++c) acc[j1][c] = mul2(GWP[0], hv[c]);
#pragma unroll
                    for (int d = 1; d < 11; ++d) {
                        const int sl = (j1 - d + 11) % 11;
#pragma unroll
                        for (int c = 0; c < 4; ++c)
                            acc[sl][c] = fma2(GWP[d], hv[c], acc[sl][c]);
                    }
                    if (r1 >= HALO && emit_col) {
                        const int es = (j1 + 1) % 11;
                        float M1[2], M2[2], BS[2], BD[2];
                        upk2(acc[es][0], M1[0], M1[1]);
                        upk2(acc[es][1], M2[0], M2[1]);
                        upk2(acc[es][2], BS[0], BS[1]);
                        upk2(acc[es][3], BD[0], BD[1]);
#pragma unroll
                        for (int col = 0; col < 2; ++col) {
                            float m1s = M1[col] * M1[col];
                            float m2s = M2[col] * M2[col];
                            float m12 = M1[col] * M2[col];
                            float sums = m1s + m2s;
                            float sigsum = fmaf(0.5f,  BS[col] + BD[col], -sums);
                            float sig12  = fmaf(0.25f, BS[col] - BD[col], -m12);
                            float num = (2.f * m12 + C1) * (2.f * sig12 + C2);
                            float den = fmaf(sums + C1, sigsum + C2, 1e-6f);
                            ssim_acc += __fdividef(num, den);
                        }
                    }
                }
            }
        }
    }

    // Block reduction
#pragma unroll
    for (int off = 16; off > 0; off >>= 1) {
        mse_acc  += __shfl_down_sync(0xffffffffu, mse_acc,  off);
        ssim_acc += __shfl_down_sync(0xffffffffu, ssim_acc, off);
    }
    const int wrp = tid >> 5, lane = tid & 31;
    if (lane == 0) { red_m[wrp] = mse_acc; red_s[wrp] = ssim_acc; }
    __syncthreads();
    if (tid == 0) {
        float m = 0.f, s = 0.f;
#pragma unroll
        for (int w = 0; w < 8; ++w) { m += red_m[w]; s += red_s[w]; }
        const int bid = blockIdx.y * NSTRIPS + blockIdx.x;
        g_partial[bid * 2 + 0] = m;
        g_partial[bid * 2 + 1] = s;
        __threadfence();
        s_ticket = atomicAdd(&g_count, 1u);
    }
    __syncthreads();

    // Last block folds in the final reduction (no 2nd launch)
    if (s_ticket == NBLOCKS - 1) {
        __threadfence();
        double m = 0.0, s = 0.0;
        for (int i = tid; i < NBLOCKS; i += NTHREADS) {
            m += (double)g_partial[i * 2 + 0];
            s += (double)g_partial[i * 2 + 1];
        }
#pragma unroll
        for (int off = 16; off > 0; off >>= 1) {
            m += __shfl_down_sync(0xffffffffu, m, off);
            s += __shfl_down_sync(0xffffffffu, s, off);
        }
        __shared__ double sm[8], ss[8];
        if (lane == 0) { sm[wrp] = m; ss[wrp] = s; }
        __syncthreads();
        if (tid == 0) {
            double M = 0.0, S = 0.0;
#pragma unroll
            for (int w = 0; w < 8; ++w) { M += sm[w]; S += ss[w]; }
            const double mse_n  = (double)NIMG * IMG_H * IMG_W;
            const double ssim_n = (double)NIMG * OUT_H * OUT_W;
            double mse_loss  = M / mse_n;
            double ssim_loss = 1.0 - S / ssim_n;
            out[0] = (float)(0.6 * mse_loss + 0.4 * ssim_loss);
            g_count = 0;   // self-reset for next graph replay
        }
    }
}

extern "C" void kernel_launch(void* const* d_in, const int* in_sizes, int n_in,
                              void* d_out, int out_size)
{
    const float* pred = (const float*)d_in[0];
    const float* targ = (const float*)d_in[1];

    dim3 grid(NSTRIPS, NIMG, 1);   // 18 x 32 = 576 blocks
    fused_mse_ssim<<<grid, NTHREADS>>>(pred, targ, (float*)d_out);
}